// round 5
// baseline (speedup 1.0000x reference)
#include <cuda_runtime.h>
#include <cuda_bf16.h>
#include <cstdint>

#define TB      128
#define TILE_H  4
#define TILE_W  32
#define CIN     64
#define COUT    64
#define HH      512
#define WW      512
#define HW      (HH * WW)

// smem layout (bytes)
// A stored [c][m], m=128, row = 256B + 16 pad = 272B
// B stored [o][c], row = 128B + 16 pad = 144B
// D staging overlays A: [ch][m] fp32, row stride 528B (132 words)
#define RS_A    272
#define RS_B    144
#define RS_DW   132
#define SM_A_HI 0
#define SM_A_LO (SM_A_HI + CIN * RS_A)       // 17408
#define SM_B_HI (SM_A_LO + CIN * RS_A)       // 34816
#define SM_B_LO (SM_B_HI + COUT * RS_B)      // 44032
#define SM_TOTAL (SM_B_LO + COUT * RS_B)     // 53248

__device__ __forceinline__ float axis_a(int i) {
    return (i == 0 || i == HH - 1) ? 0.70710678118654752f : 0.57735026918962576f;
}

__device__ __forceinline__ void ldsm_x4(uint32_t* r, uint32_t addr) {
    asm volatile("ldmatrix.sync.aligned.m8n8.x4.shared.b16 {%0,%1,%2,%3}, [%4];"
                 : "=r"(r[0]), "=r"(r[1]), "=r"(r[2]), "=r"(r[3]) : "r"(addr));
}
__device__ __forceinline__ void ldsm_x4t(uint32_t* r, uint32_t addr) {
    asm volatile("ldmatrix.sync.aligned.m8n8.x4.trans.shared.b16 {%0,%1,%2,%3}, [%4];"
                 : "=r"(r[0]), "=r"(r[1]), "=r"(r[2]), "=r"(r[3]) : "r"(addr));
}
__device__ __forceinline__ void mma_bf16(float* d, const uint32_t* a, uint32_t b0, uint32_t b1) {
    asm volatile(
        "mma.sync.aligned.m16n8k16.row.col.f32.bf16.bf16.f32 "
        "{%0,%1,%2,%3}, {%4,%5,%6,%7}, {%8,%9}, {%0,%1,%2,%3};"
        : "+f"(d[0]), "+f"(d[1]), "+f"(d[2]), "+f"(d[3])
        : "r"(a[0]), "r"(a[1]), "r"(a[2]), "r"(a[3]), "r"(b0), "r"(b1));
}

__global__ void __launch_bounds__(TB, 4) gcn_mma_kernel(
    const float* __restrict__ x,     // [B, 64, 512, 512]
    const float* __restrict__ wmat,  // [64, 64] (c, o)
    float* __restrict__ out)         // [B, 64, 512, 512]
{
    extern __shared__ __align__(128) char smem[];
    const uint32_t sb = (uint32_t)__cvta_generic_to_shared(smem);
    float* smemf = (float*)smem;
    const int tid = threadIdx.x;
    const int wid = tid >> 5;
    const int lid = tid & 31;
    const int bx = blockIdx.x, by = blockIdx.y, b = blockIdx.z;

    // ---- B tiles: W[c][o] -> smem [o][c], bf16 hi/lo split ----
    {
        const float4* w4 = (const float4*)wmat;
        #pragma unroll
        for (int i4 = tid; i4 < CIN * COUT / 4; i4 += TB) {
            int base = i4 * 4;
            int c = base >> 6, o = base & 63;
            float4 v4 = w4[i4];
            float vv[4] = {v4.x, v4.y, v4.z, v4.w};
            #pragma unroll
            for (int j = 0; j < 4; j++) {
                float v = vv[j];
                __nv_bfloat16 h = __float2bfloat16(v);
                __nv_bfloat16 l = __float2bfloat16(v - __bfloat162float(h));
                uint32_t off = (uint32_t)((o + j) * RS_B + c * 2);
                *(__nv_bfloat16*)(smem + SM_B_HI + off) = h;
                *(__nv_bfloat16*)(smem + SM_B_LO + off) = l;
            }
        }
    }

    // ---- stencil: shuffle-based horizontal sum, fold per-column weights at load ----
    const int h0 = by * TILE_H;
    const int gw = bx * TILE_W + lid;               // lane's own column (aligned warp LDG)
    const float aw = axis_a(gw);
    // halo: lane 0 covers col gw0-1, lane 31 covers col gw0+32
    const int hcol = (lid == 0) ? (bx * TILE_W - 1) : (bx * TILE_W + TILE_W);
    const bool hok = (lid == 0 || lid == 31) && ((unsigned)hcol < WW);
    const float awh = hok ? axis_a(hcol) : 0.0f;
    const float* xb = x + (size_t)b * CIN * HW;

    #pragma unroll 1
    for (int pass = 0; pass < 8; pass++) {
        const int c0 = (wid + 4 * pass) * 2;

        // batch all loads first (high MLP)
        float u[2][6], uh[2][6];
        #pragma unroll
        for (int cc = 0; cc < 2; cc++) {
            const float* pm = xb + (size_t)(c0 + cc) * HW + (size_t)(h0 - 1) * WW;
            #pragma unroll
            for (int r = 0; r < 6; r++) {
                const bool rowok = ((unsigned)(h0 - 1 + r) < HH);
                float v  = rowok ? pm[(size_t)r * WW + gw] : 0.0f;
                float vh = (rowok && hok) ? pm[(size_t)r * WW + hcol] : 0.0f;
                u[cc][r]  = v * aw;
                uh[cc][r] = vh * awh;
            }
        }

        // horizontal 3-sum via shuffles, fold vertical weight
        float hs[2][6];
        #pragma unroll
        for (int r = 0; r < 6; r++) {
            const float av = axis_a(h0 - 1 + r);
            #pragma unroll
            for (int cc = 0; cc < 2; cc++) {
                float left  = __shfl_up_sync(0xFFFFFFFFu, u[cc][r], 1);
                float right = __shfl_down_sync(0xFFFFFFFFu, u[cc][r], 1);
                if (lid == 0)  left  = uh[cc][r];
                if (lid == 31) right = uh[cc][r];
                hs[cc][r] = (left + u[cc][r] + right) * av;
            }
        }

        // vertical 3-sum, bf16 split, store into A [c][m]
        #pragma unroll
        for (int r = 0; r < TILE_H; r++) {
            float s0 = hs[0][r] + hs[0][r + 1] + hs[0][r + 2];
            float s1 = hs[1][r] + hs[1][r + 1] + hs[1][r + 2];
            __nv_bfloat16 h0b = __float2bfloat16(s0);
            __nv_bfloat16 h1b = __float2bfloat16(s1);
            __nv_bfloat16 l0b = __float2bfloat16(s0 - __bfloat162float(h0b));
            __nv_bfloat16 l1b = __float2bfloat16(s1 - __bfloat162float(h1b));
            int m = r * 32 + lid;
            uint32_t off0 = (uint32_t)(c0 * RS_A + m * 2);
            uint32_t off1 = off0 + RS_A;
            *(__nv_bfloat16*)(smem + SM_A_HI + off0) = h0b;
            *(__nv_bfloat16*)(smem + SM_A_HI + off1) = h1b;
            *(__nv_bfloat16*)(smem + SM_A_LO + off0) = l0b;
            *(__nv_bfloat16*)(smem + SM_A_LO + off1) = l1b;
        }
    }
    __syncthreads();

    // ---- MMA: D[128,64] = A * B, 3 bf16 splits, fragments loaded once per k-tile ----
    const uint32_t a_off = (uint32_t)((lid & 7) + ((lid >> 4) & 1) * 8) * RS_A
                         + (uint32_t)(wid * 32 + ((lid >> 3) & 1) * 8) * 2;
    const uint32_t b_off = (uint32_t)((lid & 7) + ((lid >> 4) & 1) * 8) * RS_B
                         + (uint32_t)(((lid >> 3) & 1) * 8) * 2;

    float acc[2][8][4];
    #pragma unroll
    for (int mt = 0; mt < 2; mt++)
        #pragma unroll
        for (int nt = 0; nt < 8; nt++)
            #pragma unroll
            for (int k = 0; k < 4; k++) acc[mt][nt][k] = 0.0f;

    #pragma unroll
    for (int kt = 0; kt < 4; kt++) {
        uint32_t bh[4][4], bl[4][4];
        #pragma unroll
        for (int p = 0; p < 4; p++) {
            ldsm_x4(bh[p], sb + SM_B_HI + b_off + (uint32_t)(p * 16 * RS_B + kt * 32));
            ldsm_x4(bl[p], sb + SM_B_LO + b_off + (uint32_t)(p * 16 * RS_B + kt * 32));
        }
        uint32_t ah[2][4], al[2][4];
        #pragma unroll
        for (int mt = 0; mt < 2; mt++) {
            ldsm_x4t(ah[mt], sb + SM_A_HI + a_off + (uint32_t)(kt * 16 * RS_A + mt * 32));
            ldsm_x4t(al[mt], sb + SM_A_LO + a_off + (uint32_t)(kt * 16 * RS_A + mt * 32));
        }
        #pragma unroll
        for (int mt = 0; mt < 2; mt++)
            #pragma unroll
            for (int nt = 0; nt < 8; nt++)
                mma_bf16(acc[mt][nt], ah[mt], bh[nt >> 1][(nt & 1) * 2], bh[nt >> 1][(nt & 1) * 2 + 1]);
        #pragma unroll
        for (int mt = 0; mt < 2; mt++)
            #pragma unroll
            for (int nt = 0; nt < 8; nt++)
                mma_bf16(acc[mt][nt], ah[mt], bl[nt >> 1][(nt & 1) * 2], bl[nt >> 1][(nt & 1) * 2 + 1]);
        #pragma unroll
        for (int mt = 0; mt < 2; mt++)
            #pragma unroll
            for (int nt = 0; nt < 8; nt++)
                mma_bf16(acc[mt][nt], al[mt], bh[nt >> 1][(nt & 1) * 2], bh[nt >> 1][(nt & 1) * 2 + 1]);
    }

    // ---- epilogue: dp-scale into smem D stage (overlays A), then coalesced STG.128 ----
    __syncthreads();   // all ldmatrix A reads done before overwrite

    const int gh = h0 + wid;                 // warp owns one image row
    const float ah_ = axis_a(gh);
    #pragma unroll
    for (int mt = 0; mt < 2; mt++) {
        #pragma unroll
        for (int half = 0; half < 2; half++) {
            int tx = mt * 16 + half * 8 + (lid >> 2);
            float dp = ah_ * axis_a(bx * TILE_W + tx);
            int m = wid * 32 + tx;
            #pragma unroll
            for (int nt = 0; nt < 8; nt++) {
                int ch = nt * 8 + (lid & 3) * 2;
                smemf[(uint32_t)(ch * RS_DW + m)]       = acc[mt][nt][half * 2 + 0] * dp;
                smemf[(uint32_t)((ch + 1) * RS_DW + m)] = acc[mt][nt][half * 2 + 1] * dp;
            }
        }
    }
    __syncthreads();

    // readback: full 128B lines per warp-instr
    float* ob = out + (size_t)b * COUT * HW + (size_t)h0 * WW + bx * TILE_W;
    #pragma unroll
    for (int i = 0; i < 16; i++) {
        int idx = tid + i * TB;
        int k = idx & 7;
        int r = (idx >> 3) & 3;
        int ch = idx >> 5;
        float4 val = *(float4*)(smemf + (uint32_t)(ch * RS_DW + r * 32 + k * 4));
        *(float4*)(ob + (size_t)ch * HW + (size_t)r * WW + k * 4) = val;
    }
}

extern "C" void kernel_launch(void* const* d_in, const int* in_sizes, int n_in,
                              void* d_out, int out_size)
{
    const float* x = (const float*)d_in[0];   // [4, 64, 512, 512]
    const float* w = (const float*)d_in[1];   // [1, 64, 64]
    float* out = (float*)d_out;

    cudaFuncSetAttribute(gcn_mma_kernel,
                         cudaFuncAttributeMaxDynamicSharedMemorySize, SM_TOTAL);

    dim3 grid(WW / TILE_W, HH / TILE_H, 4);
    gcn_mma_kernel<<<grid, TB, SM_TOTAL>>>(x, w, out);
}

// round 6
// speedup vs baseline: 1.1882x; 1.1882x over previous
#include <cuda_runtime.h>
#include <cuda_bf16.h>
#include <cstdint>

#define TB      128
#define TILE_H  4
#define TILE_W  32
#define CIN     64
#define COUT    64
#define HH      512
#define WW      512
#define HW      (HH * WW)

// smem layout (bytes)
// A stored [c][m], m=128: row = 256B + 16 pad = 272B (68 words; 4c mod 32 distinct over 8 rows)
// B stored [c][o]  (K-rows): row = 128B + 16 pad = 144B (36 words; 4c mod 32 distinct)
// D staging overlays A: [ch][m] fp32, row stride 528B (132 words)
#define RS_A    272
#define RS_B    144
#define RS_DW   132
#define SM_A_HI 0
#define SM_A_LO (SM_A_HI + CIN * RS_A)       // 17408
#define SM_B_HI (SM_A_LO + CIN * RS_A)       // 34816
#define SM_B_LO (SM_B_HI + CIN * RS_B)       // 44032
#define SM_TOTAL (SM_B_LO + CIN * RS_B)      // 53248

__device__ __forceinline__ float axis_a(int i) {
    return (i == 0 || i == HH - 1) ? 0.70710678118654752f : 0.57735026918962576f;
}

__device__ __forceinline__ void ldsm_x4t(uint32_t* r, uint32_t addr) {
    asm volatile("ldmatrix.sync.aligned.m8n8.x4.trans.shared.b16 {%0,%1,%2,%3}, [%4];"
                 : "=r"(r[0]), "=r"(r[1]), "=r"(r[2]), "=r"(r[3]) : "r"(addr));
}
__device__ __forceinline__ void mma_bf16(float* d, const uint32_t* a, uint32_t b0, uint32_t b1) {
    asm volatile(
        "mma.sync.aligned.m16n8k16.row.col.f32.bf16.bf16.f32 "
        "{%0,%1,%2,%3}, {%4,%5,%6,%7}, {%8,%9}, {%0,%1,%2,%3};"
        : "+f"(d[0]), "+f"(d[1]), "+f"(d[2]), "+f"(d[3])
        : "r"(a[0]), "r"(a[1]), "r"(a[2]), "r"(a[3]), "r"(b0), "r"(b1));
}

__global__ void __launch_bounds__(TB, 4) gcn_mma_kernel(
    const float* __restrict__ x,     // [B, 64, 512, 512]
    const float* __restrict__ wmat,  // [64, 64] (c, o)
    float* __restrict__ out)         // [B, 64, 512, 512]
{
    extern __shared__ __align__(128) char smem[];
    const uint32_t sb = (uint32_t)__cvta_generic_to_shared(smem);
    float* smemf = (float*)smem;
    const int tid = threadIdx.x;
    const int wid = tid >> 5;
    const int lid = tid & 31;
    const int bx = blockIdx.x, by = blockIdx.y, b = blockIdx.z;

    // ---- B tiles: W[c][o] -> smem [c][o] (same orientation!), bf16 hi/lo split.
    // Lane loads float2 along o, packs hi-pair / lo-pair -> contiguous 32-bit STS.
    {
        const float2* w2 = (const float2*)wmat;
        #pragma unroll
        for (int it = tid; it < CIN * COUT / 2; it += TB) {   // 16 iters/thread
            int c  = it >> 5;            // 32 float2 per 64-wide row
            int o2 = it & 31;
            float2 v = w2[it];
            __nv_bfloat16 h0 = __float2bfloat16(v.x);
            __nv_bfloat16 h1 = __float2bfloat16(v.y);
            __nv_bfloat16 l0 = __float2bfloat16(v.x - __bfloat162float(h0));
            __nv_bfloat16 l1 = __float2bfloat16(v.y - __bfloat162float(h1));
            uint32_t hp = (uint32_t)__bfloat16_as_ushort(h0) |
                          ((uint32_t)__bfloat16_as_ushort(h1) << 16);
            uint32_t lp = (uint32_t)__bfloat16_as_ushort(l0) |
                          ((uint32_t)__bfloat16_as_ushort(l1) << 16);
            uint32_t off = (uint32_t)(c * RS_B + o2 * 4);
            *(uint32_t*)(smem + SM_B_HI + off) = hp;
            *(uint32_t*)(smem + SM_B_LO + off) = lp;
        }
    }

    // ---- stencil (R4 style): batched loads, then compute; A [c][m] bf16 hi/lo ----
    const int h0 = by * TILE_H;
    const int gwl = bx * TILE_W - 1 + lid;    // left column of this lane's 3-window
    const float aw0 = ((unsigned)gwl < WW) ? axis_a(gwl) : 0.0f;
    const float aw1 = axis_a(gwl + 1);
    const float aw2 = ((unsigned)(gwl + 2) < WW) ? axis_a(gwl + 2) : 0.0f;
    const bool ok0 = ((unsigned)gwl < WW);
    const bool ok2 = ((unsigned)(gwl + 2) < WW);
    const float* xb = x + (size_t)b * CIN * HW;

    #pragma unroll 1
    for (int pass = 0; pass < 8; pass++) {
        const int c0 = (wid + 4 * pass) * 2;

        float v[2][6][3];
        #pragma unroll
        for (int cc = 0; cc < 2; cc++) {
            const float* p = xb + (size_t)(c0 + cc) * HW + (size_t)(h0 - 1) * WW + gwl;
            #pragma unroll
            for (int r = 0; r < 6; r++) {
                const bool rowok = ((unsigned)(h0 - 1 + r) < HH);
                v[cc][r][0] = (rowok && ok0) ? p[0] : 0.0f;
                v[cc][r][1] = rowok ? p[1] : 0.0f;
                v[cc][r][2] = (rowok && ok2) ? p[2] : 0.0f;
                p += WW;
            }
        }

        float hs[2][6];
        #pragma unroll
        for (int cc = 0; cc < 2; cc++) {
            #pragma unroll
            for (int r = 0; r < 6; r++) {
                float hsum = v[cc][r][1] * aw1;
                hsum = fmaf(v[cc][r][0], aw0, hsum);
                hsum = fmaf(v[cc][r][2], aw2, hsum);
                hs[cc][r] = hsum * axis_a(h0 - 1 + r);
            }
        }

        #pragma unroll
        for (int r = 0; r < TILE_H; r++) {
            float s0 = hs[0][r] + hs[0][r + 1] + hs[0][r + 2];
            float s1 = hs[1][r] + hs[1][r + 1] + hs[1][r + 2];
            __nv_bfloat16 h0b = __float2bfloat16(s0);
            __nv_bfloat16 h1b = __float2bfloat16(s1);
            __nv_bfloat16 l0b = __float2bfloat16(s0 - __bfloat162float(h0b));
            __nv_bfloat16 l1b = __float2bfloat16(s1 - __bfloat162float(h1b));
            int m = r * 32 + lid;
            uint32_t off0 = (uint32_t)(c0 * RS_A + m * 2);
            uint32_t off1 = off0 + RS_A;
            *(__nv_bfloat16*)(smem + SM_A_HI + off0) = h0b;
            *(__nv_bfloat16*)(smem + SM_A_HI + off1) = h1b;
            *(__nv_bfloat16*)(smem + SM_A_LO + off0) = l0b;
            *(__nv_bfloat16*)(smem + SM_A_LO + off1) = l1b;
        }
    }
    __syncthreads();

    // ---- MMA: D[128,64] = A * B, 3 bf16 splits, fragments loaded once per k-tile ----
    // A [k][m] trans:  reg order (m0-7,k0-7),(m8-15,k0-7),(m0-7,k8-15),(m8-15,k8-15)
    const uint32_t a_off = (uint32_t)((lid & 7) + ((lid >> 4) & 1) * 8) * RS_A
                         + (uint32_t)(wid * 32 + ((lid >> 3) & 1) * 8) * 2;
    // B [k][o] trans:  reg order (o0-7,k0-7),(o0-7,k8-15),(o8-15,k0-7),(o8-15,k8-15)
    const uint32_t b_off = (uint32_t)((lid & 7) + ((lid >> 3) & 1) * 8) * RS_B
                         + (uint32_t)(((lid >> 4) & 1) * 8) * 2;

    float acc[2][8][4];
    #pragma unroll
    for (int mt = 0; mt < 2; mt++)
        #pragma unroll
        for (int nt = 0; nt < 8; nt++)
            #pragma unroll
            for (int k = 0; k < 4; k++) acc[mt][nt][k] = 0.0f;

    #pragma unroll
    for (int kt = 0; kt < 4; kt++) {
        uint32_t bh[4][4], bl[4][4];
        #pragma unroll
        for (int p = 0; p < 4; p++) {           // p = o-block of 16
            ldsm_x4t(bh[p], sb + SM_B_HI + b_off + (uint32_t)(kt * 16 * RS_B + p * 32));
            ldsm_x4t(bl[p], sb + SM_B_LO + b_off + (uint32_t)(kt * 16 * RS_B + p * 32));
        }
        uint32_t ah[2][4], al[2][4];
        #pragma unroll
        for (int mt = 0; mt < 2; mt++) {
            ldsm_x4t(ah[mt], sb + SM_A_HI + a_off + (uint32_t)(kt * 16 * RS_A + mt * 32));
            ldsm_x4t(al[mt], sb + SM_A_LO + a_off + (uint32_t)(kt * 16 * RS_A + mt * 32));
        }
        #pragma unroll
        for (int mt = 0; mt < 2; mt++)
            #pragma unroll
            for (int nt = 0; nt < 8; nt++)
                mma_bf16(acc[mt][nt], ah[mt], bh[nt >> 1][(nt & 1) * 2], bh[nt >> 1][(nt & 1) * 2 + 1]);
        #pragma unroll
        for (int mt = 0; mt < 2; mt++)
            #pragma unroll
            for (int nt = 0; nt < 8; nt++)
                mma_bf16(acc[mt][nt], ah[mt], bl[nt >> 1][(nt & 1) * 2], bl[nt >> 1][(nt & 1) * 2 + 1]);
        #pragma unroll
        for (int mt = 0; mt < 2; mt++)
            #pragma unroll
            for (int nt = 0; nt < 8; nt++)
                mma_bf16(acc[mt][nt], al[mt], bh[nt >> 1][(nt & 1) * 2], bh[nt >> 1][(nt & 1) * 2 + 1]);
    }

    // ---- epilogue: dp-scale into smem D stage (overlays A), then coalesced STG.128 ----
    __syncthreads();   // all ldmatrix A reads done before overwrite

    const int gh = h0 + wid;                 // warp owns one image row
    const float ah_ = axis_a(gh);
    #pragma unroll
    for (int mt = 0; mt < 2; mt++) {
        #pragma unroll
        for (int half = 0; half < 2; half++) {
            int tx = mt * 16 + half * 8 + (lid >> 2);
            float dp = ah_ * axis_a(bx * TILE_W + tx);
            int m = wid * 32 + tx;
            #pragma unroll
            for (int nt = 0; nt < 8; nt++) {
                int ch = nt * 8 + (lid & 3) * 2;
                smemf[(uint32_t)(ch * RS_DW + m)]       = acc[mt][nt][half * 2 + 0] * dp;
                smemf[(uint32_t)((ch + 1) * RS_DW + m)] = acc[mt][nt][half * 2 + 1] * dp;
            }
        }
    }
    __syncthreads();

    // readback: full 128B lines per warp-instr
    float* ob = out + (size_t)b * COUT * HW + (size_t)h0 * WW + bx * TILE_W;
    #pragma unroll
    for (int i = 0; i < 16; i++) {
        int idx = tid + i * TB;
        int k = idx & 7;
        int r = (idx >> 3) & 3;
        int ch = idx >> 5;
        float4 val = *(float4*)(smemf + (uint32_t)(ch * RS_DW + r * 32 + k * 4));
        *(float4*)(ob + (size_t)ch * HW + (size_t)r * WW + k * 4) = val;
    }
}

extern "C" void kernel_launch(void* const* d_in, const int* in_sizes, int n_in,
                              void* d_out, int out_size)
{
    const float* x = (const float*)d_in[0];   // [4, 64, 512, 512]
    const float* w = (const float*)d_in[1];   // [1, 64, 64]
    float* out = (float*)d_out;

    cudaFuncSetAttribute(gcn_mma_kernel,
                         cudaFuncAttributeMaxDynamicSharedMemorySize, SM_TOTAL);

    dim3 grid(WW / TILE_W, HH / TILE_H, 4);
    gcn_mma_kernel<<<grid, TB, SM_TOTAL>>>(x, w, out);
}

// round 7
// speedup vs baseline: 1.4236x; 1.1981x over previous
#include <cuda_runtime.h>
#include <cuda_bf16.h>
#include <cstdint>

#define TB      256
#define TILE_H  8
#define TILE_W  32
#define CIN     64
#define COUT    64
#define HH      512
#define WW      512
#define HW      (HH * WW)

// smem layout (bytes)
// A stored [c][m], m=256: row = 512B + 16 pad = 528B (132 words ≡ 4 mod 32 -> conflict-free)
// B stored [c][o]: row = 128B + 16 pad = 144B (36 words ≡ 4 mod 32)
// D staging overlays A: [ch][m=256] fp32, row stride 260 words (≡ 4 mod 32)
#define RS_A    528
#define RS_B    144
#define RS_DW   260
#define SM_A_HI 0
#define SM_A_LO (SM_A_HI + CIN * RS_A)       // 33792
#define SM_B_HI (SM_A_LO + CIN * RS_A)       // 67584
#define SM_B_LO (SM_B_HI + CIN * RS_B)       // 76800
#define SM_TOTAL (SM_B_LO + CIN * RS_B)      // 86016  (2 CTAs/SM)

__device__ __forceinline__ float axis_a(int i) {
    return (i == 0 || i == HH - 1) ? 0.70710678118654752f : 0.57735026918962576f;
}

__device__ __forceinline__ void ldsm_x4t(uint32_t* r, uint32_t addr) {
    asm volatile("ldmatrix.sync.aligned.m8n8.x4.trans.shared.b16 {%0,%1,%2,%3}, [%4];"
                 : "=r"(r[0]), "=r"(r[1]), "=r"(r[2]), "=r"(r[3]) : "r"(addr));
}
__device__ __forceinline__ void mma_bf16(float* d, const uint32_t* a, uint32_t b0, uint32_t b1) {
    asm volatile(
        "mma.sync.aligned.m16n8k16.row.col.f32.bf16.bf16.f32 "
        "{%0,%1,%2,%3}, {%4,%5,%6,%7}, {%8,%9}, {%0,%1,%2,%3};"
        : "+f"(d[0]), "+f"(d[1]), "+f"(d[2]), "+f"(d[3])
        : "r"(a[0]), "r"(a[1]), "r"(a[2]), "r"(a[3]), "r"(b0), "r"(b1));
}

__global__ void __launch_bounds__(TB, 2) gcn_mma_kernel(
    const float* __restrict__ x,     // [B, 64, 512, 512]
    const float* __restrict__ wmat,  // [64, 64] (c, o)
    float* __restrict__ out)         // [B, 64, 512, 512]
{
    extern __shared__ __align__(128) char smem[];
    const uint32_t sb = (uint32_t)__cvta_generic_to_shared(smem);
    float* smemf = (float*)smem;
    const int tid = threadIdx.x;
    const int wid = tid >> 5;
    const int lid = tid & 31;
    const int bx = blockIdx.x, by = blockIdx.y, b = blockIdx.z;

    // ---- B tiles: W[c][o] -> smem [c][o], bf16 hi/lo split, coalesced 32-bit STS ----
    {
        const float2* w2 = (const float2*)wmat;
        #pragma unroll
        for (int it = tid; it < CIN * COUT / 2; it += TB) {   // 8 iters/thread
            int c  = it >> 5;
            int o2 = it & 31;
            float2 v = w2[it];
            __nv_bfloat16 h0 = __float2bfloat16(v.x);
            __nv_bfloat16 h1 = __float2bfloat16(v.y);
            __nv_bfloat16 l0 = __float2bfloat16(v.x - __bfloat162float(h0));
            __nv_bfloat16 l1 = __float2bfloat16(v.y - __bfloat162float(h1));
            uint32_t hp = (uint32_t)__bfloat16_as_ushort(h0) |
                          ((uint32_t)__bfloat16_as_ushort(h1) << 16);
            uint32_t lp = (uint32_t)__bfloat16_as_ushort(l0) |
                          ((uint32_t)__bfloat16_as_ushort(l1) << 16);
            uint32_t off = (uint32_t)(c * RS_B + o2 * 4);
            *(uint32_t*)(smem + SM_B_HI + off) = hp;
            *(uint32_t*)(smem + SM_B_LO + off) = lp;
        }
    }

    // ---- stencil: batched loads per channel, then compute; A [c][m] bf16 hi/lo ----
    const int h0 = by * TILE_H;
    const int gwl = bx * TILE_W - 1 + lid;    // left column of lane's 3-window
    const float aw0 = ((unsigned)gwl < WW) ? axis_a(gwl) : 0.0f;
    const float aw1 = axis_a(gwl + 1);
    const float aw2 = ((unsigned)(gwl + 2) < WW) ? axis_a(gwl + 2) : 0.0f;
    const bool ok0 = ((unsigned)gwl < WW);
    const bool ok2 = ((unsigned)(gwl + 2) < WW);
    const float* xb = x + (size_t)b * CIN * HW;

    #pragma unroll 1
    for (int pass = 0; pass < 4; pass++) {
        const int c0 = (wid + 8 * pass) * 2;   // pass p covers channels 16p..16p+15
        float hs[2][TILE_H + 2];

        #pragma unroll
        for (int cc = 0; cc < 2; cc++) {
            // batch this channel's 30 loads first (high MLP)
            float v[TILE_H + 2][3];
            const float* p = xb + (size_t)(c0 + cc) * HW + (size_t)(h0 - 1) * WW + gwl;
            #pragma unroll
            for (int r = 0; r < TILE_H + 2; r++) {
                const bool rowok = ((unsigned)(h0 - 1 + r) < HH);
                v[r][0] = (rowok && ok0) ? p[0] : 0.0f;
                v[r][1] = rowok ? p[1] : 0.0f;
                v[r][2] = (rowok && ok2) ? p[2] : 0.0f;
                p += WW;
            }
            #pragma unroll
            for (int r = 0; r < TILE_H + 2; r++) {
                float hsum = v[r][1] * aw1;
                hsum = fmaf(v[r][0], aw0, hsum);
                hsum = fmaf(v[r][2], aw2, hsum);
                hs[cc][r] = hsum * axis_a(h0 - 1 + r);
            }
        }

        #pragma unroll
        for (int r = 0; r < TILE_H; r++) {
            float s0 = hs[0][r] + hs[0][r + 1] + hs[0][r + 2];
            float s1 = hs[1][r] + hs[1][r + 1] + hs[1][r + 2];
            __nv_bfloat16 h0b = __float2bfloat16(s0);
            __nv_bfloat16 h1b = __float2bfloat16(s1);
            __nv_bfloat16 l0b = __float2bfloat16(s0 - __bfloat162float(h0b));
            __nv_bfloat16 l1b = __float2bfloat16(s1 - __bfloat162float(h1b));
            int m = r * 32 + lid;                     // m = row*32 + col, 0..255
            uint32_t off0 = (uint32_t)(c0 * RS_A + m * 2);
            uint32_t off1 = off0 + RS_A;
            *(__nv_bfloat16*)(smem + SM_A_HI + off0) = h0b;
            *(__nv_bfloat16*)(smem + SM_A_HI + off1) = h1b;
            *(__nv_bfloat16*)(smem + SM_A_LO + off0) = l0b;
            *(__nv_bfloat16*)(smem + SM_A_LO + off1) = l1b;
        }
    }
    __syncthreads();

    // ---- MMA: D[256,64] = A * B, 3 bf16 splits, fragments loaded once per k-tile ----
    const uint32_t a_off = (uint32_t)((lid & 7) + ((lid >> 4) & 1) * 8) * RS_A
                         + (uint32_t)(wid * 32 + ((lid >> 3) & 1) * 8) * 2;
    const uint32_t b_off = (uint32_t)((lid & 7) + ((lid >> 3) & 1) * 8) * RS_B
                         + (uint32_t)(((lid >> 4) & 1) * 8) * 2;

    float acc[2][8][4];
    #pragma unroll
    for (int mt = 0; mt < 2; mt++)
        #pragma unroll
        for (int nt = 0; nt < 8; nt++)
            #pragma unroll
            for (int k = 0; k < 4; k++) acc[mt][nt][k] = 0.0f;

    #pragma unroll
    for (int kt = 0; kt < 4; kt++) {
        uint32_t bh[4][4], bl[4][4];
        #pragma unroll
        for (int p = 0; p < 4; p++) {           // p = o-block of 16
            ldsm_x4t(bh[p], sb + SM_B_HI + b_off + (uint32_t)(kt * 16 * RS_B + p * 32));
            ldsm_x4t(bl[p], sb + SM_B_LO + b_off + (uint32_t)(kt * 16 * RS_B + p * 32));
        }
        uint32_t ah[2][4], al[2][4];
        #pragma unroll
        for (int mt = 0; mt < 2; mt++) {
            ldsm_x4t(ah[mt], sb + SM_A_HI + a_off + (uint32_t)(kt * 16 * RS_A + mt * 32));
            ldsm_x4t(al[mt], sb + SM_A_LO + a_off + (uint32_t)(kt * 16 * RS_A + mt * 32));
        }
        #pragma unroll
        for (int mt = 0; mt < 2; mt++)
            #pragma unroll
            for (int nt = 0; nt < 8; nt++)
                mma_bf16(acc[mt][nt], ah[mt], bh[nt >> 1][(nt & 1) * 2], bh[nt >> 1][(nt & 1) * 2 + 1]);
        #pragma unroll
        for (int mt = 0; mt < 2; mt++)
            #pragma unroll
            for (int nt = 0; nt < 8; nt++)
                mma_bf16(acc[mt][nt], ah[mt], bl[nt >> 1][(nt & 1) * 2], bl[nt >> 1][(nt & 1) * 2 + 1]);
        #pragma unroll
        for (int mt = 0; mt < 2; mt++)
            #pragma unroll
            for (int nt = 0; nt < 8; nt++)
                mma_bf16(acc[mt][nt], al[mt], bh[nt >> 1][(nt & 1) * 2], bh[nt >> 1][(nt & 1) * 2 + 1]);
    }

    // ---- epilogue: dp-scale into smem D stage (overlays A), then coalesced STG.128 ----
    __syncthreads();   // all ldmatrix A reads done before overwrite

    const int gh = h0 + wid;                 // warp owns one image row
    const float ah_ = axis_a(gh);
    #pragma unroll
    for (int mt = 0; mt < 2; mt++) {
        #pragma unroll
        for (int half = 0; half < 2; half++) {
            int tx = mt * 16 + half * 8 + (lid >> 2);
            float dp = ah_ * axis_a(bx * TILE_W + tx);
            int m = wid * 32 + tx;
            #pragma unroll
            for (int nt = 0; nt < 8; nt++) {
                int ch = nt * 8 + (lid & 3) * 2;
                smemf[(uint32_t)(ch * RS_DW + m)]       = acc[mt][nt][half * 2 + 0] * dp;
                smemf[(uint32_t)((ch + 1) * RS_DW + m)] = acc[mt][nt][half * 2 + 1] * dp;
            }
        }
    }
    __syncthreads();

    // readback: 4096 float4 units; warp-instr = 1 channel, 4 rows x 8 quads (full lines)
    float* ob = out + (size_t)b * COUT * HW + (size_t)h0 * WW + bx * TILE_W;
    #pragma unroll
    for (int i = 0; i < 16; i++) {
        int idx = tid + i * TB;
        int k = idx & 7;
        int r = (idx >> 3) & 7;
        int ch = idx >> 6;
        float4 val = *(float4*)(smemf + (uint32_t)(ch * RS_DW + r * 32 + k * 4));
        *(float4*)(ob + (size_t)ch * HW + (size_t)r * WW + k * 4) = val;
    }
}

extern "C" void kernel_launch(void* const* d_in, const int* in_sizes, int n_in,
                              void* d_out, int out_size)
{
    const float* x = (const float*)d_in[0];   // [4, 64, 512, 512]
    const float* w = (const float*)d_in[1];   // [1, 64, 64]
    float* out = (float*)d_out;

    cudaFuncSetAttribute(gcn_mma_kernel,
                         cudaFuncAttributeMaxDynamicSharedMemorySize, SM_TOTAL);

    dim3 grid(WW / TILE_W, HH / TILE_H, 4);
    gcn_mma_kernel<<<grid, TB, SM_TOTAL>>>(x, w, out);
}